// round 9
// baseline (speedup 1.0000x reference)
#include <cuda_runtime.h>
#include <math.h>

#define NN 50000
#define NE 800000
#define ET (NE + NN)
#define FIN 128
#define D1 128      // H*C = 4*32
#define H1 4
#define CH 32
#define SCAN_BS 1024
#define SCAN_NB ((NN + SCAN_BS - 1) / SCAN_BS)   // 49

// ---------------- scratch (device globals; no allocation allowed) -------------
__device__ float g_h1  [NN * D1];
__device__ float g_es1 [NN * H1];
__device__ float g_ed1 [NN * H1];
__device__ float g_out1[NN * D1];
__device__ float g_h2  [NN * CH];
__device__ float g_es2 [NN];
__device__ float g_ed2 [NN];
// CSR-by-dst
__device__ int   g_cnt   [NN];        // zero-init; reset inside k_scan1 each run
__device__ int   g_offs  [NN + 1];
__device__ int   g_cursor[NN];
__device__ int   g_blk   [64];        // block TOTALS (not prefixes)
__device__ int   g_srcidx[ET];

__device__ __forceinline__ float lrelu(float x) { return x > 0.f ? x : 0.2f * x; }

// ================= CSR build ====================================================
__global__ void k_count(const int* __restrict__ ei) {
    int i = blockIdx.x * blockDim.x + threadIdx.x;
    if (i < NE) atomicAdd(&g_cnt[ei[NE + i]], 1);
}

// Block-level scan of (g_cnt[i] + 1); self-loop baked in; resets g_cnt for replay.
__global__ void k_scan1() {
    __shared__ int wsum[32];
    const int t = threadIdx.x, b = blockIdx.x;
    const int i = b * SCAN_BS + t;
    const int lane = t & 31, wid = t >> 5;
    int v = 0;
    if (i < NN) { v = g_cnt[i] + 1; g_cnt[i] = 0; }
    int x = v;
#pragma unroll
    for (int o = 1; o < 32; o <<= 1) {
        int n = __shfl_up_sync(0xFFFFFFFFu, x, o);
        if (lane >= o) x += n;
    }
    if (lane == 31) wsum[wid] = x;
    __syncthreads();
    if (wid == 0) {
        int y = wsum[lane];
#pragma unroll
        for (int o = 1; o < 32; o <<= 1) {
            int n = __shfl_up_sync(0xFFFFFFFFu, y, o);
            if (lane >= o) y += n;
        }
        wsum[lane] = y;
    }
    __syncthreads();
    int excl = x - v + (wid ? wsum[wid - 1] : 0);
    if (i < NN) g_offs[i] = excl;
    if (t == SCAN_BS - 1) g_blk[b] = excl + v;   // block TOTAL
}

// Folds the top-level prefix into the final offset fixup: each block computes
// the prefix of the (<=2) scan groups it touches from the 49 block totals.
__global__ void k_scan3() {
    __shared__ int pre[2];
    const int base = blockIdx.x * blockDim.x;
    const int g0 = base >> 10;
    if (threadIdx.x < 2) {
        int g = g0 + threadIdx.x;
        int c = 0;
        for (int j = 0; j < g && j < SCAN_NB; j++) c += g_blk[j];
        pre[threadIdx.x] = c;
    }
    __syncthreads();
    const int i = base + threadIdx.x;
    if (i < NN) {
        int off = g_offs[i] + pre[(i >> 10) - g0];
        g_offs[i] = off;
        g_cursor[i] = off;
    }
    if (i == 0) g_offs[NN] = ET;
}

__global__ void k_scatter(const int* __restrict__ ei) {
    int i = blockIdx.x * blockDim.x + threadIdx.x;
    if (i >= ET) return;
    int s, d;
    if (i < NE) { s = ei[i]; d = ei[NE + i]; } else { s = d = i - NE; }
    int pos = atomicAdd(&g_cursor[d], 1);
    g_srcidx[pos] = s;
}

// ================= layer1 GEMM: 4x4 register tile, unroll 16 ====================
__global__ void k_gemm1(const float* __restrict__ x, const float* __restrict__ W1,
                        const float* __restrict__ as1, const float* __restrict__ ad1) {
    __shared__ float xs[FIN][20];
    const int t = threadIdx.x;
    const int nb = blockIdx.x * 16;
    for (int idx = t; idx < 16 * FIN; idx += 128) {
        int n = idx >> 7, k = idx & 127;
        xs[k][n] = x[(nb + n) * FIN + k];
    }
    __syncthreads();

    const int c0 = (t & 31) * 4;
    const int n0 = (t >> 5) * 4;

    float acc[4][4];
#pragma unroll
    for (int i = 0; i < 4; i++)
#pragma unroll
        for (int j = 0; j < 4; j++) acc[i][j] = 0.f;

#pragma unroll 16
    for (int k = 0; k < FIN; k++) {
        float4 xv = *(const float4*)&xs[k][n0];
        float4 wv = *(const float4*)(W1 + k * D1 + c0);
        acc[0][0] += xv.x * wv.x; acc[0][1] += xv.x * wv.y; acc[0][2] += xv.x * wv.z; acc[0][3] += xv.x * wv.w;
        acc[1][0] += xv.y * wv.x; acc[1][1] += xv.y * wv.y; acc[1][2] += xv.y * wv.z; acc[1][3] += xv.y * wv.w;
        acc[2][0] += xv.z * wv.x; acc[2][1] += xv.z * wv.y; acc[2][2] += xv.z * wv.z; acc[2][3] += xv.z * wv.w;
        acc[3][0] += xv.w * wv.x; acc[3][1] += xv.w * wv.y; acc[3][2] += xv.w * wv.z; acc[3][3] += xv.w * wv.w;
    }

    const float4 asv = *(const float4*)(as1 + c0);
    const float4 adv = *(const float4*)(ad1 + c0);
    const int lane = t & 31;
    const int head = lane >> 3;
#pragma unroll
    for (int i = 0; i < 4; i++) {
        int n = nb + n0 + i;
        *(float4*)(g_h1 + (size_t)n * D1 + c0) =
            make_float4(acc[i][0], acc[i][1], acc[i][2], acc[i][3]);
        float s = acc[i][0] * asv.x + acc[i][1] * asv.y + acc[i][2] * asv.z + acc[i][3] * asv.w;
        float d = acc[i][0] * adv.x + acc[i][1] * adv.y + acc[i][2] * adv.z + acc[i][3] * adv.w;
#pragma unroll
        for (int o = 4; o; o >>= 1) {
            s += __shfl_xor_sync(0xFFFFFFFFu, s, o);
            d += __shfl_xor_sync(0xFFFFFFFFu, d, o);
        }
        if ((lane & 7) == 0) {
            g_es1[n * H1 + head] = s;
            g_ed1[n * H1 + head] = d;
        }
    }
}

// ================= layer1 aggregation: one warp per dst =========================
__global__ void k_agg1() {
    const int gw = (blockIdx.x * blockDim.x + threadIdx.x) >> 5;   // dst node
    const int lane = threadIdx.x & 31;
    const int wi = threadIdx.x >> 5;
    __shared__ float wb[8][32][4];
    __shared__ int   sb[8][32];
    if (gw >= NN) return;

    const int beg = g_offs[gw], end = g_offs[gw + 1];
    const float4 ed = *(const float4*)(g_ed1 + gw * 4);
    float acc0 = 0.f, acc1 = 0.f, acc2 = 0.f, acc3 = 0.f;
    float den0 = 0.f, den1 = 0.f, den2 = 0.f, den3 = 0.f;

    for (int base = beg; base < end; base += 32) {
        const int cnt = min(32, end - base);
        if (lane < cnt) {
            int s = g_srcidx[base + lane];
            float4 es = *(const float4*)(g_es1 + s * 4);
            float4 wv;
            wv.x = __expf(lrelu(es.x + ed.x));
            wv.y = __expf(lrelu(es.y + ed.y));
            wv.z = __expf(lrelu(es.z + ed.z));
            wv.w = __expf(lrelu(es.w + ed.w));
            den0 += wv.x; den1 += wv.y; den2 += wv.z; den3 += wv.w;
            sb[wi][lane] = s;
            *(float4*)&wb[wi][lane][0] = wv;
        }
        __syncwarp();
        for (int j = 0; j < cnt; j++) {
            const float* hs = g_h1 + (size_t)sb[wi][j] * D1;
            float4 wj = *(const float4*)&wb[wi][j][0];
            acc0 += hs[lane]      * wj.x;
            acc1 += hs[32 + lane] * wj.y;
            acc2 += hs[64 + lane] * wj.z;
            acc3 += hs[96 + lane] * wj.w;
        }
        __syncwarp();
    }
#pragma unroll
    for (int o = 16; o; o >>= 1) {
        den0 += __shfl_xor_sync(0xFFFFFFFFu, den0, o);
        den1 += __shfl_xor_sync(0xFFFFFFFFu, den1, o);
        den2 += __shfl_xor_sync(0xFFFFFFFFu, den2, o);
        den3 += __shfl_xor_sync(0xFFFFFFFFu, den3, o);
    }
    float* od = g_out1 + (size_t)gw * D1;
    od[lane]      = acc0 / (den0 + 1e-16f);
    od[32 + lane] = acc1 / (den1 + 1e-16f);
    od[64 + lane] = acc2 / (den2 + 1e-16f);
    od[96 + lane] = acc3 / (den3 + 1e-16f);
}

// ================= finalize layer1 (+b1, relu), GEMM2, attention logits =========
__global__ void k_fin1_gemm2(const float* __restrict__ b1, const float* __restrict__ W2,
                             const float* __restrict__ as2, const float* __restrict__ ad2) {
    __shared__ float xs[16][D1];
    __shared__ float sh2[16][CH + 1];
    const int t = threadIdx.x;
    const int nb = blockIdx.x * 16;
    const float bt = b1[t];
#pragma unroll
    for (int r = 0; r < 16; r++)
        xs[r][t] = fmaxf(g_out1[(size_t)(nb + r) * D1 + t] + bt, 0.f);
    __syncthreads();

    const int c = t & 31, rg = t >> 5;
    float acc[4] = {0.f, 0.f, 0.f, 0.f};
    for (int k = 0; k < D1; k++) {
        float w = W2[k * CH + c];
        acc[0] += xs[rg     ][k] * w;
        acc[1] += xs[rg + 4 ][k] * w;
        acc[2] += xs[rg + 8 ][k] * w;
        acc[3] += xs[rg + 12][k] * w;
    }
#pragma unroll
    for (int i = 0; i < 4; i++) {
        int r = rg + 4 * i;
        g_h2[(size_t)(nb + r) * CH + c] = acc[i];
        sh2[r][c] = acc[i];
    }
    __syncthreads();

    const float as2c = as2[c], ad2c = ad2[c];
#pragma unroll
    for (int i = 0; i < 4; i++) {
        int r = rg + 4 * i;
        float s = sh2[r][c] * as2c;
        float d = sh2[r][c] * ad2c;
#pragma unroll
        for (int o = 16; o; o >>= 1) {
            s += __shfl_xor_sync(0xFFFFFFFFu, s, o);
            d += __shfl_xor_sync(0xFFFFFFFFu, d, o);
        }
        if (c == 0) { g_es2[nb + r] = s; g_ed2[nb + r] = d; }
    }
}

// ================= layer2 aggregation fused with head ===========================
__global__ void k_agg2f(const float* __restrict__ b2, const float* __restrict__ fc_w,
                        const float* __restrict__ fc_b, float* __restrict__ out) {
    const int gw = (blockIdx.x * blockDim.x + threadIdx.x) >> 5;
    const int lane = threadIdx.x & 31;
    const int wi = threadIdx.x >> 5;
    __shared__ float wb[8][32];
    __shared__ int   sb[8][32];
    if (gw >= NN) return;

    const int beg = g_offs[gw], end = g_offs[gw + 1];
    const float edv = g_ed2[gw];
    float acc = 0.f, den = 0.f;

    for (int base = beg; base < end; base += 32) {
        const int cnt = min(32, end - base);
        if (lane < cnt) {
            int s = g_srcidx[base + lane];
            float wv = __expf(lrelu(g_es2[s] + edv));
            den += wv;
            sb[wi][lane] = s;
            wb[wi][lane] = wv;
        }
        __syncwarp();
        for (int j = 0; j < cnt; j++)
            acc += g_h2[(size_t)sb[wi][j] * CH + lane] * wb[wi][j];
        __syncwarp();
    }
#pragma unroll
    for (int o = 16; o; o >>= 1)
        den += __shfl_xor_sync(0xFFFFFFFFu, den, o);

    float v = fmaxf(acc / (den + 1e-16f) + b2[lane], 0.f);
    float p = v * fc_w[lane];
#pragma unroll
    for (int o = 16; o; o >>= 1)
        p += __shfl_xor_sync(0xFFFFFFFFu, p, o);
    if (lane == 0) out[gw] = 1.f / (1.f + expf(-(p + fc_b[0])));
}

// ================= launch =======================================================
extern "C" void kernel_launch(void* const* d_in, const int* in_sizes, int n_in,
                              void* d_out, int out_size) {
    const float* x    = (const float*)d_in[0];
    const int*   ei   = (const int*)  d_in[1];
    const float* W1   = (const float*)d_in[2];
    const float* as1  = (const float*)d_in[3];
    const float* ad1  = (const float*)d_in[4];
    const float* b1   = (const float*)d_in[5];
    const float* W2   = (const float*)d_in[6];
    const float* as2  = (const float*)d_in[7];
    const float* ad2  = (const float*)d_in[8];
    const float* b2   = (const float*)d_in[9];
    const float* fc_w = (const float*)d_in[10];
    const float* fc_b = (const float*)d_in[11];
    float* out = (float*)d_out;
    (void)in_sizes; (void)n_in; (void)out_size;

    // Side stream + fork/join events, created once (handles only; no device mem).
    static cudaStream_t s2 = nullptr;
    static cudaEvent_t ev_fork = nullptr, ev_join = nullptr;
    if (!s2) {
        cudaStreamCreateWithFlags(&s2, cudaStreamNonBlocking);
        cudaEventCreateWithFlags(&ev_fork, cudaEventDisableTiming);
        cudaEventCreateWithFlags(&ev_join, cudaEventDisableTiming);
    }

    // Fork: CSR build on s2, concurrent with GEMM1 on the main (capture) stream.
    cudaEventRecord(ev_fork, 0);
    cudaStreamWaitEvent(s2, ev_fork, 0);

    k_count  <<<(NE + 255) / 256, 256, 0, s2>>>(ei);
    k_scan1  <<<SCAN_NB, SCAN_BS, 0, s2>>>();
    k_scan3  <<<(NN + 255) / 256, 256, 0, s2>>>();
    k_scatter<<<(ET + 255) / 256, 256, 0, s2>>>(ei);
    cudaEventRecord(ev_join, s2);

    k_gemm1<<<NN / 16, 128>>>(x, W1, as1, ad1);

    // Join: agg1 needs both CSR and h1/es1/ed1.
    cudaStreamWaitEvent(0, ev_join, 0);

    k_agg1      <<<(NN * 32 + 255) / 256, 256>>>();
    k_fin1_gemm2<<<NN / 16, 128>>>(b1, W2, as2, ad2);
    k_agg2f     <<<(NN * 32 + 255) / 256, 256>>>(b2, fc_w, fc_b, out);
}

// round 11
// speedup vs baseline: 1.0895x; 1.0895x over previous
#include <cuda_runtime.h>
#include <math.h>

#define NN 50000
#define NE 800000
#define ET (NE + NN)
#define FIN 128
#define D1 128      // H*C = 4*32
#define H1 4
#define CH 32
#define SCAN_BS 1024
#define SCAN_NB ((NN + SCAN_BS - 1) / SCAN_BS)   // 49

// ---------------- scratch (device globals; no allocation allowed) -------------
__device__ float g_h1  [NN * D1];
__device__ float g_es1 [NN * H1];
__device__ float g_ed1 [NN * H1];
__device__ float g_out1[NN * D1];
__device__ float g_h2  [NN * CH];
__device__ float g_es2 [NN];
__device__ float g_ed2 [NN];
// CSR-by-dst
__device__ int   g_cnt   [NN];        // zero-init; reset inside k_scan1 each run
__device__ int   g_offs  [NN + 1];
__device__ int   g_cursor[NN];
__device__ int   g_blk   [64];        // block TOTALS (not prefixes)
__device__ int   g_srcidx[ET];

__device__ __forceinline__ float lrelu(float x) { return x > 0.f ? x : 0.2f * x; }

// ================= CSR build ====================================================
__global__ void k_count(const int* __restrict__ ei) {
    int i = blockIdx.x * blockDim.x + threadIdx.x;
    if (i < NE) atomicAdd(&g_cnt[ei[NE + i]], 1);
}

// Block-level scan of (g_cnt[i] + 1); self-loop baked in; resets g_cnt for replay.
__global__ void k_scan1() {
    __shared__ int wsum[32];
    const int t = threadIdx.x, b = blockIdx.x;
    const int i = b * SCAN_BS + t;
    const int lane = t & 31, wid = t >> 5;
    int v = 0;
    if (i < NN) { v = g_cnt[i] + 1; g_cnt[i] = 0; }
    int x = v;
#pragma unroll
    for (int o = 1; o < 32; o <<= 1) {
        int n = __shfl_up_sync(0xFFFFFFFFu, x, o);
        if (lane >= o) x += n;
    }
    if (lane == 31) wsum[wid] = x;
    __syncthreads();
    if (wid == 0) {
        int y = wsum[lane];
#pragma unroll
        for (int o = 1; o < 32; o <<= 1) {
            int n = __shfl_up_sync(0xFFFFFFFFu, y, o);
            if (lane >= o) y += n;
        }
        wsum[lane] = y;
    }
    __syncthreads();
    int excl = x - v + (wid ? wsum[wid - 1] : 0);
    if (i < NN) g_offs[i] = excl;
    if (t == SCAN_BS - 1) g_blk[b] = excl + v;   // block TOTAL
}

// Folds the top-level prefix into the final offset fixup: each block computes
// the prefix of the (<=2) scan groups it touches from the 49 block totals.
__global__ void k_scan3() {
    __shared__ int pre[2];
    const int base = blockIdx.x * blockDim.x;
    const int g0 = base >> 10;
    if (threadIdx.x < 2) {
        int g = g0 + threadIdx.x;
        int c = 0;
        for (int j = 0; j < g && j < SCAN_NB; j++) c += g_blk[j];
        pre[threadIdx.x] = c;
    }
    __syncthreads();
    const int i = base + threadIdx.x;
    if (i < NN) {
        int off = g_offs[i] + pre[(i >> 10) - g0];
        g_offs[i] = off;
        g_cursor[i] = off;
    }
    if (i == 0) g_offs[NN] = ET;
}

__global__ void k_scatter(const int* __restrict__ ei) {
    int i = blockIdx.x * blockDim.x + threadIdx.x;
    if (i >= ET) return;
    int s, d;
    if (i < NE) { s = ei[i]; d = ei[NE + i]; } else { s = d = i - NE; }
    int pos = atomicAdd(&g_cursor[d], 1);
    g_srcidx[pos] = s;
}

// ================= layer1 GEMM: 4x4 register tile, unroll 8 =====================
// Block: 128 threads, 16 nodes x 128 cols. Thread (c0=(t%32)*4, n0=(t/32)*4)
// computes acc[4 nodes][4 cols]. xs transposed [k][node], row padded to 20 floats.
// unroll 8: ptxas front-batches 8 independent LDG.128/LDS.128 pairs (MLP~8).
// (unroll 16 measured SLOWER: register pressure past the sweet spot.)
__global__ void k_gemm1(const float* __restrict__ x, const float* __restrict__ W1,
                        const float* __restrict__ as1, const float* __restrict__ ad1) {
    __shared__ float xs[FIN][20];
    const int t = threadIdx.x;
    const int nb = blockIdx.x * 16;
    for (int idx = t; idx < 16 * FIN; idx += 128) {
        int n = idx >> 7, k = idx & 127;
        xs[k][n] = x[(nb + n) * FIN + k];
    }
    __syncthreads();

    const int c0 = (t & 31) * 4;
    const int n0 = (t >> 5) * 4;

    float acc[4][4];
#pragma unroll
    for (int i = 0; i < 4; i++)
#pragma unroll
        for (int j = 0; j < 4; j++) acc[i][j] = 0.f;

#pragma unroll 8
    for (int k = 0; k < FIN; k++) {
        float4 xv = *(const float4*)&xs[k][n0];
        float4 wv = *(const float4*)(W1 + k * D1 + c0);
        acc[0][0] += xv.x * wv.x; acc[0][1] += xv.x * wv.y; acc[0][2] += xv.x * wv.z; acc[0][3] += xv.x * wv.w;
        acc[1][0] += xv.y * wv.x; acc[1][1] += xv.y * wv.y; acc[1][2] += xv.y * wv.z; acc[1][3] += xv.y * wv.w;
        acc[2][0] += xv.z * wv.x; acc[2][1] += xv.z * wv.y; acc[2][2] += xv.z * wv.z; acc[2][3] += xv.z * wv.w;
        acc[3][0] += xv.w * wv.x; acc[3][1] += xv.w * wv.y; acc[3][2] += xv.w * wv.z; acc[3][3] += xv.w * wv.w;
    }

    const float4 asv = *(const float4*)(as1 + c0);
    const float4 adv = *(const float4*)(ad1 + c0);
    const int lane = t & 31;
    const int head = lane >> 3;
#pragma unroll
    for (int i = 0; i < 4; i++) {
        int n = nb + n0 + i;
        *(float4*)(g_h1 + (size_t)n * D1 + c0) =
            make_float4(acc[i][0], acc[i][1], acc[i][2], acc[i][3]);
        float s = acc[i][0] * asv.x + acc[i][1] * asv.y + acc[i][2] * asv.z + acc[i][3] * asv.w;
        float d = acc[i][0] * adv.x + acc[i][1] * adv.y + acc[i][2] * adv.z + acc[i][3] * adv.w;
#pragma unroll
        for (int o = 4; o; o >>= 1) {
            s += __shfl_xor_sync(0xFFFFFFFFu, s, o);
            d += __shfl_xor_sync(0xFFFFFFFFu, d, o);
        }
        if ((lane & 7) == 0) {
            g_es1[n * H1 + head] = s;
            g_ed1[n * H1 + head] = d;
        }
    }
}

// ================= layer1 aggregation: one warp per dst =========================
__global__ void k_agg1() {
    const int gw = (blockIdx.x * blockDim.x + threadIdx.x) >> 5;   // dst node
    const int lane = threadIdx.x & 31;
    const int wi = threadIdx.x >> 5;
    __shared__ float wb[8][32][4];
    __shared__ int   sb[8][32];
    if (gw >= NN) return;

    const int beg = g_offs[gw], end = g_offs[gw + 1];
    const float4 ed = *(const float4*)(g_ed1 + gw * 4);
    float acc0 = 0.f, acc1 = 0.f, acc2 = 0.f, acc3 = 0.f;
    float den0 = 0.f, den1 = 0.f, den2 = 0.f, den3 = 0.f;

    for (int base = beg; base < end; base += 32) {
        const int cnt = min(32, end - base);
        if (lane < cnt) {
            int s = g_srcidx[base + lane];
            float4 es = *(const float4*)(g_es1 + s * 4);
            float4 wv;
            wv.x = __expf(lrelu(es.x + ed.x));
            wv.y = __expf(lrelu(es.y + ed.y));
            wv.z = __expf(lrelu(es.z + ed.z));
            wv.w = __expf(lrelu(es.w + ed.w));
            den0 += wv.x; den1 += wv.y; den2 += wv.z; den3 += wv.w;
            sb[wi][lane] = s;
            *(float4*)&wb[wi][lane][0] = wv;
        }
        __syncwarp();
        for (int j = 0; j < cnt; j++) {
            const float* hs = g_h1 + (size_t)sb[wi][j] * D1;
            float4 wj = *(const float4*)&wb[wi][j][0];
            acc0 += hs[lane]      * wj.x;
            acc1 += hs[32 + lane] * wj.y;
            acc2 += hs[64 + lane] * wj.z;
            acc3 += hs[96 + lane] * wj.w;
        }
        __syncwarp();
    }
#pragma unroll
    for (int o = 16; o; o >>= 1) {
        den0 += __shfl_xor_sync(0xFFFFFFFFu, den0, o);
        den1 += __shfl_xor_sync(0xFFFFFFFFu, den1, o);
        den2 += __shfl_xor_sync(0xFFFFFFFFu, den2, o);
        den3 += __shfl_xor_sync(0xFFFFFFFFu, den3, o);
    }
    float* od = g_out1 + (size_t)gw * D1;
    od[lane]      = acc0 / (den0 + 1e-16f);
    od[32 + lane] = acc1 / (den1 + 1e-16f);
    od[64 + lane] = acc2 / (den2 + 1e-16f);
    od[96 + lane] = acc3 / (den3 + 1e-16f);
}

// ================= finalize layer1 (+b1, relu), GEMM2, attention logits =========
__global__ void k_fin1_gemm2(const float* __restrict__ b1, const float* __restrict__ W2,
                             const float* __restrict__ as2, const float* __restrict__ ad2) {
    __shared__ float xs[16][D1];
    __shared__ float sh2[16][CH + 1];
    const int t = threadIdx.x;
    const int nb = blockIdx.x * 16;
    const float bt = b1[t];
#pragma unroll
    for (int r = 0; r < 16; r++)
        xs[r][t] = fmaxf(g_out1[(size_t)(nb + r) * D1 + t] + bt, 0.f);
    __syncthreads();

    const int c = t & 31, rg = t >> 5;
    float acc[4] = {0.f, 0.f, 0.f, 0.f};
    for (int k = 0; k < D1; k++) {
        float w = W2[k * CH + c];
        acc[0] += xs[rg     ][k] * w;
        acc[1] += xs[rg + 4 ][k] * w;
        acc[2] += xs[rg + 8 ][k] * w;
        acc[3] += xs[rg + 12][k] * w;
    }
#pragma unroll
    for (int i = 0; i < 4; i++) {
        int r = rg + 4 * i;
        g_h2[(size_t)(nb + r) * CH + c] = acc[i];
        sh2[r][c] = acc[i];
    }
    __syncthreads();

    const float as2c = as2[c], ad2c = ad2[c];
#pragma unroll
    for (int i = 0; i < 4; i++) {
        int r = rg + 4 * i;
        float s = sh2[r][c] * as2c;
        float d = sh2[r][c] * ad2c;
#pragma unroll
        for (int o = 16; o; o >>= 1) {
            s += __shfl_xor_sync(0xFFFFFFFFu, s, o);
            d += __shfl_xor_sync(0xFFFFFFFFu, d, o);
        }
        if (c == 0) { g_es2[nb + r] = s; g_ed2[nb + r] = d; }
    }
}

// ================= layer2 aggregation fused with head ===========================
__global__ void k_agg2f(const float* __restrict__ b2, const float* __restrict__ fc_w,
                        const float* __restrict__ fc_b, float* __restrict__ out) {
    const int gw = (blockIdx.x * blockDim.x + threadIdx.x) >> 5;
    const int lane = threadIdx.x & 31;
    const int wi = threadIdx.x >> 5;
    __shared__ float wb[8][32];
    __shared__ int   sb[8][32];
    if (gw >= NN) return;

    const int beg = g_offs[gw], end = g_offs[gw + 1];
    const float edv = g_ed2[gw];
    float acc = 0.f, den = 0.f;

    for (int base = beg; base < end; base += 32) {
        const int cnt = min(32, end - base);
        if (lane < cnt) {
            int s = g_srcidx[base + lane];
            float wv = __expf(lrelu(g_es2[s] + edv));
            den += wv;
            sb[wi][lane] = s;
            wb[wi][lane] = wv;
        }
        __syncwarp();
        for (int j = 0; j < cnt; j++)
            acc += g_h2[(size_t)sb[wi][j] * CH + lane] * wb[wi][j];
        __syncwarp();
    }
#pragma unroll
    for (int o = 16; o; o >>= 1)
        den += __shfl_xor_sync(0xFFFFFFFFu, den, o);

    float v = fmaxf(acc / (den + 1e-16f) + b2[lane], 0.f);
    float p = v * fc_w[lane];
#pragma unroll
    for (int o = 16; o; o >>= 1)
        p += __shfl_xor_sync(0xFFFFFFFFu, p, o);
    if (lane == 0) out[gw] = 1.f / (1.f + expf(-(p + fc_b[0])));
}

// ================= launch =======================================================
extern "C" void kernel_launch(void* const* d_in, const int* in_sizes, int n_in,
                              void* d_out, int out_size) {
    const float* x    = (const float*)d_in[0];
    const int*   ei   = (const int*)  d_in[1];
    const float* W1   = (const float*)d_in[2];
    const float* as1  = (const float*)d_in[3];
    const float* ad1  = (const float*)d_in[4];
    const float* b1   = (const float*)d_in[5];
    const float* W2   = (const float*)d_in[6];
    const float* as2  = (const float*)d_in[7];
    const float* ad2  = (const float*)d_in[8];
    const float* b2   = (const float*)d_in[9];
    const float* fc_w = (const float*)d_in[10];
    const float* fc_b = (const float*)d_in[11];
    float* out = (float*)d_out;
    (void)in_sizes; (void)n_in; (void)out_size;

    // Side stream + fork/join events, created once (handles only; no device mem).
    static cudaStream_t s2 = nullptr;
    static cudaEvent_t ev_fork = nullptr, ev_join = nullptr;
    if (!s2) {
        cudaStreamCreateWithFlags(&s2, cudaStreamNonBlocking);
        cudaEventCreateWithFlags(&ev_fork, cudaEventDisableTiming);
        cudaEventCreateWithFlags(&ev_join, cudaEventDisableTiming);
    }

    // Fork: CSR build on s2, concurrent with GEMM1 on the main (capture) stream.
    cudaEventRecord(ev_fork, 0);
    cudaStreamWaitEvent(s2, ev_fork, 0);

    k_count  <<<(NE + 255) / 256, 256, 0, s2>>>(ei);
    k_scan1  <<<SCAN_NB, SCAN_BS, 0, s2>>>();
    k_scan3  <<<(NN + 255) / 256, 256, 0, s2>>>();
    k_scatter<<<(ET + 255) / 256, 256, 0, s2>>>(ei);
    cudaEventRecord(ev_join, s2);

    k_gemm1<<<NN / 16, 128>>>(x, W1, as1, ad1);

    // Join: agg1 needs both CSR and h1/es1/ed1.
    cudaStreamWaitEvent(0, ev_join, 0);

    k_agg1      <<<(NN * 32 + 255) / 256, 256>>>();
    k_fin1_gemm2<<<NN / 16, 128>>>(b1, W2, as2, ad2);
    k_agg2f     <<<(NN * 32 + 255) / 256, 256>>>(b2, fc_w, fc_b, out);
}

// round 12
// speedup vs baseline: 1.1338x; 1.0407x over previous
#include <cuda_runtime.h>
#include <cuda_fp16.h>
#include <math.h>

#define NN 50000
#define NE 800000
#define ET (NE + NN)
#define FIN 128
#define D1 128      // H*C = 4*32
#define H1 4
#define CH 32
#define SCAN_BS 1024
#define SCAN_NB ((NN + SCAN_BS - 1) / SCAN_BS)   // 49

// ---------------- scratch (device globals; no allocation allowed) -------------
__device__ __half g_h1h[NN * D1];     // fp16 h1 (gather-bound -> half the bytes)
__device__ float  g_es1 [NN * H1];
__device__ float  g_ed1 [NN * H1];
__device__ float  g_out1[NN * D1];
__device__ __half g_h2h[NN * CH];     // fp16 h2
__device__ float  g_es2 [NN];
__device__ float  g_ed2 [NN];
// CSR-by-dst
__device__ int    g_cnt   [NN];       // zero-init; reset inside k_scan1 each run
__device__ int    g_offs  [NN + 1];
__device__ int    g_cursor[NN];
__device__ int    g_blk   [64];       // block TOTALS (not prefixes)
__device__ int    g_srcidx[ET];

__device__ __forceinline__ float lrelu(float x) { return x > 0.f ? x : 0.2f * x; }

// ================= CSR build ====================================================
__global__ void k_count(const int* __restrict__ ei) {
    int i = blockIdx.x * blockDim.x + threadIdx.x;
    if (i < NE) atomicAdd(&g_cnt[ei[NE + i]], 1);
}

// Block-level scan of (g_cnt[i] + 1); self-loop baked in; resets g_cnt for replay.
__global__ void k_scan1() {
    __shared__ int wsum[32];
    const int t = threadIdx.x, b = blockIdx.x;
    const int i = b * SCAN_BS + t;
    const int lane = t & 31, wid = t >> 5;
    int v = 0;
    if (i < NN) { v = g_cnt[i] + 1; g_cnt[i] = 0; }
    int x = v;
#pragma unroll
    for (int o = 1; o < 32; o <<= 1) {
        int n = __shfl_up_sync(0xFFFFFFFFu, x, o);
        if (lane >= o) x += n;
    }
    if (lane == 31) wsum[wid] = x;
    __syncthreads();
    if (wid == 0) {
        int y = wsum[lane];
#pragma unroll
        for (int o = 1; o < 32; o <<= 1) {
            int n = __shfl_up_sync(0xFFFFFFFFu, y, o);
            if (lane >= o) y += n;
        }
        wsum[lane] = y;
    }
    __syncthreads();
    int excl = x - v + (wid ? wsum[wid - 1] : 0);
    if (i < NN) g_offs[i] = excl;
    if (t == SCAN_BS - 1) g_blk[b] = excl + v;   // block TOTAL
}

// Folds the top-level prefix into the final offset fixup.
__global__ void k_scan3() {
    __shared__ int pre[2];
    const int base = blockIdx.x * blockDim.x;
    const int g0 = base >> 10;
    if (threadIdx.x < 2) {
        int g = g0 + threadIdx.x;
        int c = 0;
        for (int j = 0; j < g && j < SCAN_NB; j++) c += g_blk[j];
        pre[threadIdx.x] = c;
    }
    __syncthreads();
    const int i = base + threadIdx.x;
    if (i < NN) {
        int off = g_offs[i] + pre[(i >> 10) - g0];
        g_offs[i] = off;
        g_cursor[i] = off;
    }
    if (i == 0) g_offs[NN] = ET;
}

__global__ void k_scatter(const int* __restrict__ ei) {
    int i = blockIdx.x * blockDim.x + threadIdx.x;
    if (i >= ET) return;
    int s, d;
    if (i < NE) { s = ei[i]; d = ei[NE + i]; } else { s = d = i - NE; }
    int pos = atomicAdd(&g_cursor[d], 1);
    g_srcidx[pos] = s;
}

// ================= layer1 GEMM: 4x4 register tile, unroll 8 =====================
// fp32 compute; h1 stored as fp16 (halves downstream gather traffic).
__global__ void k_gemm1(const float* __restrict__ x, const float* __restrict__ W1,
                        const float* __restrict__ as1, const float* __restrict__ ad1) {
    __shared__ float xs[FIN][20];
    const int t = threadIdx.x;
    const int nb = blockIdx.x * 16;
    for (int idx = t; idx < 16 * FIN; idx += 128) {
        int n = idx >> 7, k = idx & 127;
        xs[k][n] = x[(nb + n) * FIN + k];
    }
    __syncthreads();

    const int c0 = (t & 31) * 4;
    const int n0 = (t >> 5) * 4;

    float acc[4][4];
#pragma unroll
    for (int i = 0; i < 4; i++)
#pragma unroll
        for (int j = 0; j < 4; j++) acc[i][j] = 0.f;

#pragma unroll 8
    for (int k = 0; k < FIN; k++) {
        float4 xv = *(const float4*)&xs[k][n0];
        float4 wv = *(const float4*)(W1 + k * D1 + c0);
        acc[0][0] += xv.x * wv.x; acc[0][1] += xv.x * wv.y; acc[0][2] += xv.x * wv.z; acc[0][3] += xv.x * wv.w;
        acc[1][0] += xv.y * wv.x; acc[1][1] += xv.y * wv.y; acc[1][2] += xv.y * wv.z; acc[1][3] += xv.y * wv.w;
        acc[2][0] += xv.z * wv.x; acc[2][1] += xv.z * wv.y; acc[2][2] += xv.z * wv.z; acc[2][3] += xv.z * wv.w;
        acc[3][0] += xv.w * wv.x; acc[3][1] += xv.w * wv.y; acc[3][2] += xv.w * wv.z; acc[3][3] += xv.w * wv.w;
    }

    const float4 asv = *(const float4*)(as1 + c0);
    const float4 adv = *(const float4*)(ad1 + c0);
    const int lane = t & 31;
    const int head = lane >> 3;
#pragma unroll
    for (int i = 0; i < 4; i++) {
        int n = nb + n0 + i;
        __half2 p0 = __floats2half2_rn(acc[i][0], acc[i][1]);
        __half2 p1 = __floats2half2_rn(acc[i][2], acc[i][3]);
        uint2 pk;
        pk.x = *(unsigned*)&p0;
        pk.y = *(unsigned*)&p1;
        *(uint2*)(g_h1h + (size_t)n * D1 + c0) = pk;   // 8B aligned: c0 % 4 == 0
        float s = acc[i][0] * asv.x + acc[i][1] * asv.y + acc[i][2] * asv.z + acc[i][3] * asv.w;
        float d = acc[i][0] * adv.x + acc[i][1] * adv.y + acc[i][2] * adv.z + acc[i][3] * adv.w;
#pragma unroll
        for (int o = 4; o; o >>= 1) {
            s += __shfl_xor_sync(0xFFFFFFFFu, s, o);
            d += __shfl_xor_sync(0xFFFFFFFFu, d, o);
        }
        if ((lane & 7) == 0) {
            g_es1[n * H1 + head] = s;
            g_ed1[n * H1 + head] = d;
        }
    }
}

// NOTE: the attention logits (es1/ed1) above are computed from the PRE-quantized
// fp32 acc. The aggregation uses the fp16 h values. Reference uses identical h
// for both; error stays ~fp16 quantization of h only (~1e-4 rel), within 1e-3.

// ================= layer1 aggregation: one warp per dst =========================
__global__ void k_agg1() {
    const int gw = (blockIdx.x * blockDim.x + threadIdx.x) >> 5;   // dst node
    const int lane = threadIdx.x & 31;
    const int wi = threadIdx.x >> 5;
    __shared__ float wb[8][32][4];
    __shared__ int   sb[8][32];
    if (gw >= NN) return;

    const int beg = g_offs[gw], end = g_offs[gw + 1];
    const float4 ed = *(const float4*)(g_ed1 + gw * 4);
    float acc0 = 0.f, acc1 = 0.f, acc2 = 0.f, acc3 = 0.f;
    float den0 = 0.f, den1 = 0.f, den2 = 0.f, den3 = 0.f;

    for (int base = beg; base < end; base += 32) {
        const int cnt = min(32, end - base);
        if (lane < cnt) {
            int s = g_srcidx[base + lane];
            float4 es = *(const float4*)(g_es1 + s * 4);
            float4 wv;
            wv.x = __expf(lrelu(es.x + ed.x));
            wv.y = __expf(lrelu(es.y + ed.y));
            wv.z = __expf(lrelu(es.z + ed.z));
            wv.w = __expf(lrelu(es.w + ed.w));
            den0 += wv.x; den1 += wv.y; den2 += wv.z; den3 += wv.w;
            sb[wi][lane] = s;
            *(float4*)&wb[wi][lane][0] = wv;
        }
        __syncwarp();
        for (int j = 0; j < cnt; j++) {
            const __half* hs = g_h1h + (size_t)sb[wi][j] * D1;
            float4 wj = *(const float4*)&wb[wi][j][0];
            acc0 += __half2float(hs[lane])      * wj.x;
            acc1 += __half2float(hs[32 + lane]) * wj.y;
            acc2 += __half2float(hs[64 + lane]) * wj.z;
            acc3 += __half2float(hs[96 + lane]) * wj.w;
        }
        __syncwarp();
    }
#pragma unroll
    for (int o = 16; o; o >>= 1) {
        den0 += __shfl_xor_sync(0xFFFFFFFFu, den0, o);
        den1 += __shfl_xor_sync(0xFFFFFFFFu, den1, o);
        den2 += __shfl_xor_sync(0xFFFFFFFFu, den2, o);
        den3 += __shfl_xor_sync(0xFFFFFFFFu, den3, o);
    }
    float* od = g_out1 + (size_t)gw * D1;
    od[lane]      = acc0 / (den0 + 1e-16f);
    od[32 + lane] = acc1 / (den1 + 1e-16f);
    od[64 + lane] = acc2 / (den2 + 1e-16f);
    od[96 + lane] = acc3 / (den3 + 1e-16f);
}

// ================= finalize layer1 (+b1, relu), GEMM2, attention logits =========
__global__ void k_fin1_gemm2(const float* __restrict__ b1, const float* __restrict__ W2,
                             const float* __restrict__ as2, const float* __restrict__ ad2) {
    __shared__ float xs[16][D1];
    __shared__ float sh2[16][CH + 1];
    const int t = threadIdx.x;
    const int nb = blockIdx.x * 16;
    const float bt = b1[t];
#pragma unroll
    for (int r = 0; r < 16; r++)
        xs[r][t] = fmaxf(g_out1[(size_t)(nb + r) * D1 + t] + bt, 0.f);
    __syncthreads();

    const int c = t & 31, rg = t >> 5;
    float acc[4] = {0.f, 0.f, 0.f, 0.f};
    for (int k = 0; k < D1; k++) {
        float w = W2[k * CH + c];
        acc[0] += xs[rg     ][k] * w;
        acc[1] += xs[rg + 4 ][k] * w;
        acc[2] += xs[rg + 8 ][k] * w;
        acc[3] += xs[rg + 12][k] * w;
    }
#pragma unroll
    for (int i = 0; i < 4; i++) {
        int r = rg + 4 * i;
        g_h2h[(size_t)(nb + r) * CH + c] = __float2half(acc[i]);
        sh2[r][c] = acc[i];
    }
    __syncthreads();

    const float as2c = as2[c], ad2c = ad2[c];
#pragma unroll
    for (int i = 0; i < 4; i++) {
        int r = rg + 4 * i;
        float s = sh2[r][c] * as2c;
        float d = sh2[r][c] * ad2c;
#pragma unroll
        for (int o = 16; o; o >>= 1) {
            s += __shfl_xor_sync(0xFFFFFFFFu, s, o);
            d += __shfl_xor_sync(0xFFFFFFFFu, d, o);
        }
        if (c == 0) { g_es2[nb + r] = s; g_ed2[nb + r] = d; }
    }
}

// ================= layer2 aggregation fused with head ===========================
__global__ void k_agg2f(const float* __restrict__ b2, const float* __restrict__ fc_w,
                        const float* __restrict__ fc_b, float* __restrict__ out) {
    const int gw = (blockIdx.x * blockDim.x + threadIdx.x) >> 5;
    const int lane = threadIdx.x & 31;
    const int wi = threadIdx.x >> 5;
    __shared__ float wb[8][32];
    __shared__ int   sb[8][32];
    if (gw >= NN) return;

    const int beg = g_offs[gw], end = g_offs[gw + 1];
    const float edv = g_ed2[gw];
    float acc = 0.f, den = 0.f;

    for (int base = beg; base < end; base += 32) {
        const int cnt = min(32, end - base);
        if (lane < cnt) {
            int s = g_srcidx[base + lane];
            float wv = __expf(lrelu(g_es2[s] + edv));
            den += wv;
            sb[wi][lane] = s;
            wb[wi][lane] = wv;
        }
        __syncwarp();
        for (int j = 0; j < cnt; j++)
            acc += __half2float(g_h2h[(size_t)sb[wi][j] * CH + lane]) * wb[wi][j];
        __syncwarp();
    }
#pragma unroll
    for (int o = 16; o; o >>= 1)
        den += __shfl_xor_sync(0xFFFFFFFFu, den, o);

    float v = fmaxf(acc / (den + 1e-16f) + b2[lane], 0.f);
    float p = v * fc_w[lane];
#pragma unroll
    for (int o = 16; o; o >>= 1)
        p += __shfl_xor_sync(0xFFFFFFFFu, p, o);
    if (lane == 0) out[gw] = 1.f / (1.f + expf(-(p + fc_b[0])));
}

// ================= launch =======================================================
extern "C" void kernel_launch(void* const* d_in, const int* in_sizes, int n_in,
                              void* d_out, int out_size) {
    const float* x    = (const float*)d_in[0];
    const int*   ei   = (const int*)  d_in[1];
    const float* W1   = (const float*)d_in[2];
    const float* as1  = (const float*)d_in[3];
    const float* ad1  = (const float*)d_in[4];
    const float* b1   = (const float*)d_in[5];
    const float* W2   = (const float*)d_in[6];
    const float* as2  = (const float*)d_in[7];
    const float* ad2  = (const float*)d_in[8];
    const float* b2   = (const float*)d_in[9];
    const float* fc_w = (const float*)d_in[10];
    const float* fc_b = (const float*)d_in[11];
    float* out = (float*)d_out;
    (void)in_sizes; (void)n_in; (void)out_size;

    // Side stream + fork/join events, created once (handles only; no device mem).
    static cudaStream_t s2 = nullptr;
    static cudaEvent_t ev_fork = nullptr, ev_join = nullptr;
    if (!s2) {
        cudaStreamCreateWithFlags(&s2, cudaStreamNonBlocking);
        cudaEventCreateWithFlags(&ev_fork, cudaEventDisableTiming);
        cudaEventCreateWithFlags(&ev_join, cudaEventDisableTiming);
    }

    // Fork: CSR build on s2, concurrent with GEMM1 on the main (capture) stream.
    cudaEventRecord(ev_fork, 0);
    cudaStreamWaitEvent(s2, ev_fork, 0);

    k_count  <<<(NE + 255) / 256, 256, 0, s2>>>(ei);
    k_scan1  <<<SCAN_NB, SCAN_BS, 0, s2>>>();
    k_scan3  <<<(NN + 255) / 256, 256, 0, s2>>>();
    k_scatter<<<(ET + 255) / 256, 256, 0, s2>>>(ei);
    cudaEventRecord(ev_join, s2);

    k_gemm1<<<NN / 16, 128>>>(x, W1, as1, ad1);

    // Join: agg1 needs both CSR and h1/es1/ed1.
    cudaStreamWaitEvent(0, ev_join, 0);

    k_agg1      <<<(NN * 32 + 255) / 256, 256>>>();
    k_fin1_gemm2<<<NN / 16, 128>>>(b1, W2, as2, ad2);
    k_agg2f     <<<(NN * 32 + 255) / 256, 256>>>(b2, fc_w, fc_b, out);
}

// round 14
// speedup vs baseline: 1.2483x; 1.1010x over previous
#include <cuda_runtime.h>
#include <cuda_fp16.h>
#include <math.h>

#define NN 50000
#define NE 800000
#define ET (NE + NN)
#define FIN 128
#define D1 128      // H*C = 4*32
#define H1 4
#define CH 32
#define SCAN_BS 1024
#define SCAN_NB ((NN + SCAN_BS - 1) / SCAN_BS)   // 49

// ---------------- scratch (device globals; no allocation allowed) -------------
__device__ __half g_h1h[NN * D1];     // fp16 h1 (gather-bound -> half the bytes)
__device__ float  g_es1 [NN * H1];
__device__ float  g_ed1 [NN * H1];
__device__ float  g_out1[NN * D1];
__device__ __half g_h2h[NN * CH];     // fp16 h2
__device__ float  g_es2 [NN];
__device__ float  g_ed2 [NN];
// CSR-by-dst
__device__ int    g_cnt   [NN];       // zero-init; reset inside k_scan1 each run
__device__ int    g_offs  [NN + 1];
__device__ int    g_cursor[NN];
__device__ int    g_blk   [64];       // block TOTALS (not prefixes)
__device__ int    g_srcidx[ET];

__device__ __forceinline__ float lrelu(float x) { return x > 0.f ? x : 0.2f * x; }

// ================= CSR build ====================================================
__global__ void k_count(const int* __restrict__ ei) {
    int i = blockIdx.x * blockDim.x + threadIdx.x;
    if (i < NE) atomicAdd(&g_cnt[ei[NE + i]], 1);
}

// Block-level scan of (g_cnt[i] + 1); self-loop baked in; resets g_cnt for replay.
__global__ void k_scan1() {
    __shared__ int wsum[32];
    const int t = threadIdx.x, b = blockIdx.x;
    const int i = b * SCAN_BS + t;
    const int lane = t & 31, wid = t >> 5;
    int v = 0;
    if (i < NN) { v = g_cnt[i] + 1; g_cnt[i] = 0; }
    int x = v;
#pragma unroll
    for (int o = 1; o < 32; o <<= 1) {
        int n = __shfl_up_sync(0xFFFFFFFFu, x, o);
        if (lane >= o) x += n;
    }
    if (lane == 31) wsum[wid] = x;
    __syncthreads();
    if (wid == 0) {
        int y = wsum[lane];
#pragma unroll
        for (int o = 1; o < 32; o <<= 1) {
            int n = __shfl_up_sync(0xFFFFFFFFu, y, o);
            if (lane >= o) y += n;
        }
        wsum[lane] = y;
    }
    __syncthreads();
    int excl = x - v + (wid ? wsum[wid - 1] : 0);
    if (i < NN) g_offs[i] = excl;
    if (t == SCAN_BS - 1) g_blk[b] = excl + v;   // block TOTAL
}

// Folds the top-level prefix into the final offset fixup.
__global__ void k_scan3() {
    __shared__ int pre[2];
    const int base = blockIdx.x * blockDim.x;
    const int g0 = base >> 10;
    if (threadIdx.x < 2) {
        int g = g0 + threadIdx.x;
        int c = 0;
        for (int j = 0; j < g && j < SCAN_NB; j++) c += g_blk[j];
        pre[threadIdx.x] = c;
    }
    __syncthreads();
    const int i = base + threadIdx.x;
    if (i < NN) {
        int off = g_offs[i] + pre[(i >> 10) - g0];
        g_offs[i] = off;
        g_cursor[i] = off;
    }
    if (i == 0) g_offs[NN] = ET;
}

__global__ void k_scatter(const int* __restrict__ ei) {
    int i = blockIdx.x * blockDim.x + threadIdx.x;
    if (i >= ET) return;
    int s, d;
    if (i < NE) { s = ei[i]; d = ei[NE + i]; } else { s = d = i - NE; }
    int pos = atomicAdd(&g_cursor[d], 1);
    g_srcidx[pos] = s;
}

// ================= layer1 GEMM: 4x4 register tile, unroll 8 =====================
// fp32 compute; h1 stored as fp16 (halves downstream gather traffic).
__global__ void k_gemm1(const float* __restrict__ x, const float* __restrict__ W1,
                        const float* __restrict__ as1, const float* __restrict__ ad1) {
    __shared__ float xs[FIN][20];
    const int t = threadIdx.x;
    const int nb = blockIdx.x * 16;
    for (int idx = t; idx < 16 * FIN; idx += 128) {
        int n = idx >> 7, k = idx & 127;
        xs[k][n] = x[(nb + n) * FIN + k];
    }
    __syncthreads();

    const int c0 = (t & 31) * 4;
    const int n0 = (t >> 5) * 4;

    float acc[4][4];
#pragma unroll
    for (int i = 0; i < 4; i++)
#pragma unroll
        for (int j = 0; j < 4; j++) acc[i][j] = 0.f;

#pragma unroll 8
    for (int k = 0; k < FIN; k++) {
        float4 xv = *(const float4*)&xs[k][n0];
        float4 wv = *(const float4*)(W1 + k * D1 + c0);
        acc[0][0] += xv.x * wv.x; acc[0][1] += xv.x * wv.y; acc[0][2] += xv.x * wv.z; acc[0][3] += xv.x * wv.w;
        acc[1][0] += xv.y * wv.x; acc[1][1] += xv.y * wv.y; acc[1][2] += xv.y * wv.z; acc[1][3] += xv.y * wv.w;
        acc[2][0] += xv.z * wv.x; acc[2][1] += xv.z * wv.y; acc[2][2] += xv.z * wv.z; acc[2][3] += xv.z * wv.w;
        acc[3][0] += xv.w * wv.x; acc[3][1] += xv.w * wv.y; acc[3][2] += xv.w * wv.z; acc[3][3] += xv.w * wv.w;
    }

    const float4 asv = *(const float4*)(as1 + c0);
    const float4 adv = *(const float4*)(ad1 + c0);
    const int lane = t & 31;
    const int head = lane >> 3;
#pragma unroll
    for (int i = 0; i < 4; i++) {
        int n = nb + n0 + i;
        __half2 p0 = __floats2half2_rn(acc[i][0], acc[i][1]);
        __half2 p1 = __floats2half2_rn(acc[i][2], acc[i][3]);
        uint2 pk;
        pk.x = *(unsigned*)&p0;
        pk.y = *(unsigned*)&p1;
        *(uint2*)(g_h1h + (size_t)n * D1 + c0) = pk;   // 8B aligned: c0 % 4 == 0
        float s = acc[i][0] * asv.x + acc[i][1] * asv.y + acc[i][2] * asv.z + acc[i][3] * asv.w;
        float d = acc[i][0] * adv.x + acc[i][1] * adv.y + acc[i][2] * adv.z + acc[i][3] * adv.w;
#pragma unroll
        for (int o = 4; o; o >>= 1) {
            s += __shfl_xor_sync(0xFFFFFFFFu, s, o);
            d += __shfl_xor_sync(0xFFFFFFFFu, d, o);
        }
        if ((lane & 7) == 0) {
            g_es1[n * H1 + head] = s;
            g_ed1[n * H1 + head] = d;
        }
    }
}

// ================= layer1 aggregation: one warp per dst, vectorized gather ======
// Lane l owns contiguous channels [4l, 4l+3] (all in head l>>3):
// per edge it's ONE LDG.64 + one broadcast LDS.32 instead of 4 scattered LDG.U16.
__global__ void k_agg1() {
    const int gw = (blockIdx.x * blockDim.x + threadIdx.x) >> 5;   // dst node
    const int lane = threadIdx.x & 31;
    const int wi = threadIdx.x >> 5;
    __shared__ float wb[8][32][4];
    __shared__ int   sb[8][32];
    if (gw >= NN) return;

    const int beg = g_offs[gw], end = g_offs[gw + 1];
    const float4 ed = *(const float4*)(g_ed1 + gw * 4);
    const int head = lane >> 3;
    float acc0 = 0.f, acc1 = 0.f, acc2 = 0.f, acc3 = 0.f;
    float den0 = 0.f, den1 = 0.f, den2 = 0.f, den3 = 0.f;

    for (int base = beg; base < end; base += 32) {
        const int cnt = min(32, end - base);
        if (lane < cnt) {
            int s = g_srcidx[base + lane];
            float4 es = *(const float4*)(g_es1 + s * 4);
            float4 wv;
            wv.x = __expf(lrelu(es.x + ed.x));
            wv.y = __expf(lrelu(es.y + ed.y));
            wv.z = __expf(lrelu(es.z + ed.z));
            wv.w = __expf(lrelu(es.w + ed.w));
            den0 += wv.x; den1 += wv.y; den2 += wv.z; den3 += wv.w;
            sb[wi][lane] = s;
            *(float4*)&wb[wi][lane][0] = wv;
        }
        __syncwarp();
#pragma unroll 4
        for (int j = 0; j < cnt; j++) {
            uint2 p = *(const uint2*)(g_h1h + (size_t)sb[wi][j] * D1 + 4 * lane);
            float w = wb[wi][j][head];                      // broadcast within 8-lane group
            float2 f01 = __half22float2(*(__half2*)&p.x);
            float2 f23 = __half22float2(*(__half2*)&p.y);
            acc0 += f01.x * w;
            acc1 += f01.y * w;
            acc2 += f23.x * w;
            acc3 += f23.y * w;
        }
        __syncwarp();
    }
#pragma unroll
    for (int o = 16; o; o >>= 1) {
        den0 += __shfl_xor_sync(0xFFFFFFFFu, den0, o);
        den1 += __shfl_xor_sync(0xFFFFFFFFu, den1, o);
        den2 += __shfl_xor_sync(0xFFFFFFFFu, den2, o);
        den3 += __shfl_xor_sync(0xFFFFFFFFu, den3, o);
    }
    float den = (head == 0) ? den0 : (head == 1) ? den1 : (head == 2) ? den2 : den3;
    float inv = 1.f / (den + 1e-16f);
    *(float4*)(g_out1 + (size_t)gw * D1 + 4 * lane) =
        make_float4(acc0 * inv, acc1 * inv, acc2 * inv, acc3 * inv);
}

// ================= finalize layer1 (+b1, relu), GEMM2, attention logits =========
__global__ void k_fin1_gemm2(const float* __restrict__ b1, const float* __restrict__ W2,
                             const float* __restrict__ as2, const float* __restrict__ ad2) {
    __shared__ float xs[16][D1];
    __shared__ float sh2[16][CH + 1];
    const int t = threadIdx.x;
    const int nb = blockIdx.x * 16;
    const float bt = b1[t];
#pragma unroll
    for (int r = 0; r < 16; r++)
        xs[r][t] = fmaxf(g_out1[(size_t)(nb + r) * D1 + t] + bt, 0.f);
    __syncthreads();

    const int c = t & 31, rg = t >> 5;
    float acc[4] = {0.f, 0.f, 0.f, 0.f};
    for (int k = 0; k < D1; k++) {
        float w = W2[k * CH + c];
        acc[0] += xs[rg     ][k] * w;
        acc[1] += xs[rg + 4 ][k] * w;
        acc[2] += xs[rg + 8 ][k] * w;
        acc[3] += xs[rg + 12][k] * w;
    }
#pragma unroll
    for (int i = 0; i < 4; i++) {
        int r = rg + 4 * i;
        g_h2h[(size_t)(nb + r) * CH + c] = __float2half(acc[i]);
        sh2[r][c] = acc[i];
    }
    __syncthreads();

    const float as2c = as2[c], ad2c = ad2[c];
#pragma unroll
    for (int i = 0; i < 4; i++) {
        int r = rg + 4 * i;
        float s = sh2[r][c] * as2c;
        float d = sh2[r][c] * ad2c;
#pragma unroll
        for (int o = 16; o; o >>= 1) {
            s += __shfl_xor_sync(0xFFFFFFFFu, s, o);
            d += __shfl_xor_sync(0xFFFFFFFFu, d, o);
        }
        if (c == 0) { g_es2[nb + r] = s; g_ed2[nb + r] = d; }
    }
}

// ================= layer2 aggregation fused with head ===========================
__global__ void k_agg2f(const float* __restrict__ b2, const float* __restrict__ fc_w,
                        const float* __restrict__ fc_b, float* __restrict__ out) {
    const int gw = (blockIdx.x * blockDim.x + threadIdx.x) >> 5;
    const int lane = threadIdx.x & 31;
    const int wi = threadIdx.x >> 5;
    __shared__ float wb[8][32];
    __shared__ int   sb[8][32];
    if (gw >= NN) return;

    const int beg = g_offs[gw], end = g_offs[gw + 1];
    const float edv = g_ed2[gw];
    float acc = 0.f, den = 0.f;

    for (int base = beg; base < end; base += 32) {
        const int cnt = min(32, end - base);
        if (lane < cnt) {
            int s = g_srcidx[base + lane];
            float wv = __expf(lrelu(g_es2[s] + edv));
            den += wv;
            sb[wi][lane] = s;
            wb[wi][lane] = wv;
        }
        __syncwarp();
#pragma unroll 4
        for (int j = 0; j < cnt; j++)
            acc += __half2float(g_h2h[(size_t)sb[wi][j] * CH + lane]) * wb[wi][j];
        __syncwarp();
    }
#pragma unroll
    for (int o = 16; o; o >>= 1)
        den += __shfl_xor_sync(0xFFFFFFFFu, den, o);

    float v = fmaxf(acc / (den + 1e-16f) + b2[lane], 0.f);
    float p = v * fc_w[lane];
#pragma unroll
    for (int o = 16; o; o >>= 1)
        p += __shfl_xor_sync(0xFFFFFFFFu, p, o);
    if (lane == 0) out[gw] = 1.f / (1.f + expf(-(p + fc_b[0])));
}

// ================= launch =======================================================
extern "C" void kernel_launch(void* const* d_in, const int* in_sizes, int n_in,
                              void* d_out, int out_size) {
    const float* x    = (const float*)d_in[0];
    const int*   ei   = (const int*)  d_in[1];
    const float* W1   = (const float*)d_in[2];
    const float* as1  = (const float*)d_in[3];
    const float* ad1  = (const float*)d_in[4];
    const float* b1   = (const float*)d_in[5];
    const float* W2   = (const float*)d_in[6];
    const float* as2  = (const float*)d_in[7];
    const float* ad2  = (const float*)d_in[8];
    const float* b2   = (const float*)d_in[9];
    const float* fc_w = (const float*)d_in[10];
    const float* fc_b = (const float*)d_in[11];
    float* out = (float*)d_out;
    (void)in_sizes; (void)n_in; (void)out_size;

    // Side stream + fork/join events, created once (handles only; no device mem).
    static cudaStream_t s2 = nullptr;
    static cudaEvent_t ev_fork = nullptr, ev_join = nullptr;
    if (!s2) {
        cudaStreamCreateWithFlags(&s2, cudaStreamNonBlocking);
        cudaEventCreateWithFlags(&ev_fork, cudaEventDisableTiming);
        cudaEventCreateWithFlags(&ev_join, cudaEventDisableTiming);
    }

    // Fork: CSR build on s2, concurrent with GEMM1 on the main (capture) stream.
    cudaEventRecord(ev_fork, 0);
    cudaStreamWaitEvent(s2, ev_fork, 0);

    k_count  <<<(NE + 255) / 256, 256, 0, s2>>>(ei);
    k_scan1  <<<SCAN_NB, SCAN_BS, 0, s2>>>();
    k_scan3  <<<(NN + 255) / 256, 256, 0, s2>>>();
    k_scatter<<<(ET + 255) / 256, 256, 0, s2>>>(ei);
    cudaEventRecord(ev_join, s2);

    k_gemm1<<<NN / 16, 128>>>(x, W1, as1, ad1);

    // Join: agg1 needs both CSR and h1/es1/ed1.
    cudaStreamWaitEvent(0, ev_join, 0);

    k_agg1      <<<(NN * 32 + 255) / 256, 256>>>();
    k_fin1_gemm2<<<NN / 16, 128>>>(b1, W2, as2, ad2);
    k_agg2f     <<<(NN * 32 + 255) / 256, 256>>>(b2, fc_w, fc_b, out);
}

// round 15
// speedup vs baseline: 1.3220x; 1.0590x over previous
#include <cuda_runtime.h>
#include <cuda_fp16.h>
#include <math.h>

#define NN 50000
#define NE 800000
#define ET (NE + NN)
#define FIN 128
#define D1 128      // H*C = 4*32
#define H1 4
#define CH 32
#define SCAN_BS 1024
#define SCAN_NB ((NN + SCAN_BS - 1) / SCAN_BS)   // 49

// ---------------- scratch (device globals; no allocation allowed) -------------
__device__ __half g_h1h [NN * D1];    // fp16 h1
__device__ float  g_es1 [NN * H1];
__device__ float  g_ed1 [NN * H1];
__device__ __half g_out1h[NN * D1];   // fp16 out1 (was fp32)
__device__ __half g_h2h [NN * CH];    // fp16 h2
__device__ float  g_es2 [NN];
__device__ float  g_ed2 [NN];
// CSR-by-dst
__device__ int    g_cnt   [NN];       // zero-init; reset inside k_scan1 each run
__device__ int    g_offs  [NN + 1];
__device__ int    g_cursor[NN];
__device__ int    g_blk   [64];       // block TOTALS (not prefixes)
__device__ int    g_srcidx[ET];

__device__ __forceinline__ float lrelu(float x) { return x > 0.f ? x : 0.2f * x; }

// ================= CSR build ====================================================
__global__ void k_count(const int* __restrict__ ei) {
    int i = blockIdx.x * blockDim.x + threadIdx.x;
    if (i < NE) atomicAdd(&g_cnt[ei[NE + i]], 1);
}

__global__ void k_scan1() {
    __shared__ int wsum[32];
    const int t = threadIdx.x, b = blockIdx.x;
    const int i = b * SCAN_BS + t;
    const int lane = t & 31, wid = t >> 5;
    int v = 0;
    if (i < NN) { v = g_cnt[i] + 1; g_cnt[i] = 0; }
    int x = v;
#pragma unroll
    for (int o = 1; o < 32; o <<= 1) {
        int n = __shfl_up_sync(0xFFFFFFFFu, x, o);
        if (lane >= o) x += n;
    }
    if (lane == 31) wsum[wid] = x;
    __syncthreads();
    if (wid == 0) {
        int y = wsum[lane];
#pragma unroll
        for (int o = 1; o < 32; o <<= 1) {
            int n = __shfl_up_sync(0xFFFFFFFFu, y, o);
            if (lane >= o) y += n;
        }
        wsum[lane] = y;
    }
    __syncthreads();
    int excl = x - v + (wid ? wsum[wid - 1] : 0);
    if (i < NN) g_offs[i] = excl;
    if (t == SCAN_BS - 1) g_blk[b] = excl + v;   // block TOTAL
}

__global__ void k_scan3() {
    __shared__ int pre[2];
    const int base = blockIdx.x * blockDim.x;
    const int g0 = base >> 10;
    if (threadIdx.x < 2) {
        int g = g0 + threadIdx.x;
        int c = 0;
        for (int j = 0; j < g && j < SCAN_NB; j++) c += g_blk[j];
        pre[threadIdx.x] = c;
    }
    __syncthreads();
    const int i = base + threadIdx.x;
    if (i < NN) {
        int off = g_offs[i] + pre[(i >> 10) - g0];
        g_offs[i] = off;
        g_cursor[i] = off;
    }
    if (i == 0) g_offs[NN] = ET;
}

__global__ void k_scatter(const int* __restrict__ ei) {
    int i = blockIdx.x * blockDim.x + threadIdx.x;
    if (i >= ET) return;
    int s, d;
    if (i < NE) { s = ei[i]; d = ei[NE + i]; } else { s = d = i - NE; }
    int pos = atomicAdd(&g_cursor[d], 1);
    g_srcidx[pos] = s;
}

// ================= layer1 GEMM: 4x4 register tile, unroll 8 =====================
__global__ void k_gemm1(const float* __restrict__ x, const float* __restrict__ W1,
                        const float* __restrict__ as1, const float* __restrict__ ad1) {
    __shared__ float xs[FIN][20];
    const int t = threadIdx.x;
    const int nb = blockIdx.x * 16;
    for (int idx = t; idx < 16 * FIN; idx += 128) {
        int n = idx >> 7, k = idx & 127;
        xs[k][n] = x[(nb + n) * FIN + k];
    }
    __syncthreads();

    const int c0 = (t & 31) * 4;
    const int n0 = (t >> 5) * 4;

    float acc[4][4];
#pragma unroll
    for (int i = 0; i < 4; i++)
#pragma unroll
        for (int j = 0; j < 4; j++) acc[i][j] = 0.f;

#pragma unroll 8
    for (int k = 0; k < FIN; k++) {
        float4 xv = *(const float4*)&xs[k][n0];
        float4 wv = *(const float4*)(W1 + k * D1 + c0);
        acc[0][0] += xv.x * wv.x; acc[0][1] += xv.x * wv.y; acc[0][2] += xv.x * wv.z; acc[0][3] += xv.x * wv.w;
        acc[1][0] += xv.y * wv.x; acc[1][1] += xv.y * wv.y; acc[1][2] += xv.y * wv.z; acc[1][3] += xv.y * wv.w;
        acc[2][0] += xv.z * wv.x; acc[2][1] += xv.z * wv.y; acc[2][2] += xv.z * wv.z; acc[2][3] += xv.z * wv.w;
        acc[3][0] += xv.w * wv.x; acc[3][1] += xv.w * wv.y; acc[3][2] += xv.w * wv.z; acc[3][3] += xv.w * wv.w;
    }

    const float4 asv = *(const float4*)(as1 + c0);
    const float4 adv = *(const float4*)(ad1 + c0);
    const int lane = t & 31;
    const int head = lane >> 3;
#pragma unroll
    for (int i = 0; i < 4; i++) {
        int n = nb + n0 + i;
        __half2 p0 = __floats2half2_rn(acc[i][0], acc[i][1]);
        __half2 p1 = __floats2half2_rn(acc[i][2], acc[i][3]);
        uint2 pk;
        pk.x = *(unsigned*)&p0;
        pk.y = *(unsigned*)&p1;
        *(uint2*)(g_h1h + (size_t)n * D1 + c0) = pk;
        float s = acc[i][0] * asv.x + acc[i][1] * asv.y + acc[i][2] * asv.z + acc[i][3] * asv.w;
        float d = acc[i][0] * adv.x + acc[i][1] * adv.y + acc[i][2] * adv.z + acc[i][3] * adv.w;
#pragma unroll
        for (int o = 4; o; o >>= 1) {
            s += __shfl_xor_sync(0xFFFFFFFFu, s, o);
            d += __shfl_xor_sync(0xFFFFFFFFu, d, o);
        }
        if ((lane & 7) == 0) {
            g_es1[n * H1 + head] = s;
            g_ed1[n * H1 + head] = d;
        }
    }
}

// ================= layer1 aggregation: one warp per dst, vectorized gather ======
__global__ void k_agg1() {
    const int gw = (blockIdx.x * blockDim.x + threadIdx.x) >> 5;   // dst node
    const int lane = threadIdx.x & 31;
    const int wi = threadIdx.x >> 5;
    __shared__ float wb[8][32][4];
    __shared__ int   sb[8][32];
    if (gw >= NN) return;

    const int beg = g_offs[gw], end = g_offs[gw + 1];
    const float4 ed = *(const float4*)(g_ed1 + gw * 4);
    const int head = lane >> 3;
    float acc0 = 0.f, acc1 = 0.f, acc2 = 0.f, acc3 = 0.f;
    float den0 = 0.f, den1 = 0.f, den2 = 0.f, den3 = 0.f;

    for (int base = beg; base < end; base += 32) {
        const int cnt = min(32, end - base);
        if (lane < cnt) {
            int s = g_srcidx[base + lane];
            float4 es = *(const float4*)(g_es1 + s * 4);
            float4 wv;
            wv.x = __expf(lrelu(es.x + ed.x));
            wv.y = __expf(lrelu(es.y + ed.y));
            wv.z = __expf(lrelu(es.z + ed.z));
            wv.w = __expf(lrelu(es.w + ed.w));
            den0 += wv.x; den1 += wv.y; den2 += wv.z; den3 += wv.w;
            sb[wi][lane] = s;
            *(float4*)&wb[wi][lane][0] = wv;
        }
        __syncwarp();
#pragma unroll 4
        for (int j = 0; j < cnt; j++) {
            uint2 p = *(const uint2*)(g_h1h + (size_t)sb[wi][j] * D1 + 4 * lane);
            float w = wb[wi][j][head];
            float2 f01 = __half22float2(*(__half2*)&p.x);
            float2 f23 = __half22float2(*(__half2*)&p.y);
            acc0 += f01.x * w;
            acc1 += f01.y * w;
            acc2 += f23.x * w;
            acc3 += f23.y * w;
        }
        __syncwarp();
    }
#pragma unroll
    for (int o = 16; o; o >>= 1) {
        den0 += __shfl_xor_sync(0xFFFFFFFFu, den0, o);
        den1 += __shfl_xor_sync(0xFFFFFFFFu, den1, o);
        den2 += __shfl_xor_sync(0xFFFFFFFFu, den2, o);
        den3 += __shfl_xor_sync(0xFFFFFFFFu, den3, o);
    }
    float den = (head == 0) ? den0 : (head == 1) ? den1 : (head == 2) ? den2 : den3;
    float inv = 1.f / (den + 1e-16f);
    __half2 q0 = __floats2half2_rn(acc0 * inv, acc1 * inv);
    __half2 q1 = __floats2half2_rn(acc2 * inv, acc3 * inv);
    uint2 pk;
    pk.x = *(unsigned*)&q0;
    pk.y = *(unsigned*)&q1;
    *(uint2*)(g_out1h + (size_t)gw * D1 + 4 * lane) = pk;
}

// ================= finalize layer1 (+b1, relu), GEMM2, attention logits =========
__global__ void k_fin1_gemm2(const float* __restrict__ b1, const float* __restrict__ W2,
                             const float* __restrict__ as2, const float* __restrict__ ad2) {
    __shared__ float xs[16][D1];
    __shared__ float sh2[16][CH + 1];
    const int t = threadIdx.x;
    const int nb = blockIdx.x * 16;
    const float bt = b1[t];
#pragma unroll
    for (int r = 0; r < 16; r++)
        xs[r][t] = fmaxf(__half2float(g_out1h[(size_t)(nb + r) * D1 + t]) + bt, 0.f);
    __syncthreads();

    const int c = t & 31, rg = t >> 5;
    float acc[4] = {0.f, 0.f, 0.f, 0.f};
    for (int k = 0; k < D1; k++) {
        float w = W2[k * CH + c];
        acc[0] += xs[rg     ][k] * w;
        acc[1] += xs[rg + 4 ][k] * w;
        acc[2] += xs[rg + 8 ][k] * w;
        acc[3] += xs[rg + 12][k] * w;
    }
#pragma unroll
    for (int i = 0; i < 4; i++) {
        int r = rg + 4 * i;
        g_h2h[(size_t)(nb + r) * CH + c] = __float2half(acc[i]);
        sh2[r][c] = acc[i];
    }
    __syncthreads();

    const float as2c = as2[c], ad2c = ad2[c];
#pragma unroll
    for (int i = 0; i < 4; i++) {
        int r = rg + 4 * i;
        float s = sh2[r][c] * as2c;
        float d = sh2[r][c] * ad2c;
#pragma unroll
        for (int o = 16; o; o >>= 1) {
            s += __shfl_xor_sync(0xFFFFFFFFu, s, o);
            d += __shfl_xor_sync(0xFFFFFFFFu, d, o);
        }
        if (c == 0) { g_es2[nb + r] = s; g_ed2[nb + r] = d; }
    }
}

// ================= layer2 aggregation fused with head ===========================
// Two edges per iteration: lanes 0-15 handle edge j, lanes 16-31 edge j+1.
// Each lane loads one half2 (channels 2(l&15), +1) -> half the LDGs, 2x MLP.
__global__ void k_agg2f(const float* __restrict__ b2, const float* __restrict__ fc_w,
                        const float* __restrict__ fc_b, float* __restrict__ out) {
    const int gw = (blockIdx.x * blockDim.x + threadIdx.x) >> 5;
    const int lane = threadIdx.x & 31;
    const int wi = threadIdx.x >> 5;
    __shared__ float wb[8][32];
    __shared__ int   sb[8][32];
    if (gw >= NN) return;

    const int beg = g_offs[gw], end = g_offs[gw + 1];
    const float edv = g_ed2[gw];
    const int c2 = (lane & 15) * 2;
    const int esel = lane >> 4;
    float acc0 = 0.f, acc1 = 0.f, den = 0.f;

    for (int base = beg; base < end; base += 32) {
        const int cnt = min(32, end - base);
        if (lane < cnt) {
            int s = g_srcidx[base + lane];
            float wv = __expf(lrelu(g_es2[s] + edv));
            den += wv;
            sb[wi][lane] = s;
            wb[wi][lane] = wv;
        }
        __syncwarp();
#pragma unroll 4
        for (int j = 0; j < cnt; j += 2) {
            int e = j + esel;
            if (e < cnt) {
                __half2 hv = *(const __half2*)(g_h2h + (size_t)sb[wi][e] * CH + c2);
                float w = wb[wi][e];
                float2 f = __half22float2(hv);
                acc0 += f.x * w;
                acc1 += f.y * w;
            }
        }
        __syncwarp();
    }
#pragma unroll
    for (int o = 16; o; o >>= 1)
        den += __shfl_xor_sync(0xFFFFFFFFu, den, o);
    // merge the two edge-groups (lane l and l+16 accumulate the same channels)
    acc0 += __shfl_xor_sync(0xFFFFFFFFu, acc0, 16);
    acc1 += __shfl_xor_sync(0xFFFFFFFFu, acc1, 16);

    float inv = 1.f / (den + 1e-16f);
    float v0 = fmaxf(acc0 * inv + b2[c2],     0.f);
    float v1 = fmaxf(acc1 * inv + b2[c2 + 1], 0.f);
    float p = v0 * fc_w[c2] + v1 * fc_w[c2 + 1];
#pragma unroll
    for (int o = 8; o; o >>= 1)           // reduce within 16-lane group only
        p += __shfl_xor_sync(0xFFFFFFFFu, p, o);
    if (lane == 0) out[gw] = 1.f / (1.f + expf(-(p + fc_b[0])));
}

// ================= launch =======================================================
extern "C" void kernel_launch(void* const* d_in, const int* in_sizes, int n_in,
                              void* d_out, int out_size) {
    const float* x    = (const float*)d_in[0];
    const int*   ei   = (const int*)  d_in[1];
    const float* W1   = (const float*)d_in[2];
    const float* as1  = (const float*)d_in[3];
    const float* ad1  = (const float*)d_in[4];
    const float* b1   = (const float*)d_in[5];
    const float* W2   = (const float*)d_in[6];
    const float* as2  = (const float*)d_in[7];
    const float* ad2  = (const float*)d_in[8];
    const float* b2   = (const float*)d_in[9];
    const float* fc_w = (const float*)d_in[10];
    const float* fc_b = (const float*)d_in[11];
    float* out = (float*)d_out;
    (void)in_sizes; (void)n_in; (void)out_size;

    // Side stream + fork/join events, created once (handles only; no device mem).
    static cudaStream_t s2 = nullptr;
    static cudaEvent_t ev_fork = nullptr, ev_join = nullptr;
    if (!s2) {
        cudaStreamCreateWithFlags(&s2, cudaStreamNonBlocking);
        cudaEventCreateWithFlags(&ev_fork, cudaEventDisableTiming);
        cudaEventCreateWithFlags(&ev_join, cudaEventDisableTiming);
    }

    // Fork: CSR build on s2, concurrent with GEMM1 on the main (capture) stream.
    cudaEventRecord(ev_fork, 0);
    cudaStreamWaitEvent(s2, ev_fork, 0);

    k_count  <<<(NE + 255) / 256, 256, 0, s2>>>(ei);
    k_scan1  <<<SCAN_NB, SCAN_BS, 0, s2>>>();
    k_scan3  <<<(NN + 255) / 256, 256, 0, s2>>>();
    k_scatter<<<(ET + 255) / 256, 256, 0, s2>>>(ei);
    cudaEventRecord(ev_join, s2);

    k_gemm1<<<NN / 16, 128>>>(x, W1, as1, ad1);

    // Join: agg1 needs both CSR and h1/es1/ed1.
    cudaStreamWaitEvent(0, ev_join, 0);

    k_agg1      <<<(NN * 32 + 255) / 256, 256>>>();
    k_fin1_gemm2<<<NN / 16, 128>>>(b1, W2, as2, ad2);
    k_agg2f     <<<(NN * 32 + 255) / 256, 256>>>(b2, fc_w, fc_b, out);
}